// round 17
// baseline (speedup 1.0000x reference)
#include <cuda_runtime.h>
#include <cuda_fp16.h>
#include <cstdint>

// Problem shape (fixed): B=64, T=1000, I=512, O=256
#define SNN_B 64
#define SNN_T 1000
#define SNN_I 512
#define SNN_O 256
#define ALPHA 0.95f
#define BETA  0.9f

#define CHUNKS 10
#define CHUNK_L 100
#define MROWS (SNN_B * SNN_T)     // 64000
#define NTILES (SNN_B * CHUNKS)   // 640

__device__ __half   g_h[(size_t)MROWS * SNN_O];
__device__ float4   g_end[NTILES * 128];    // per (b,chunk): 128 x {f0,o0,f1,o1}
__device__ uint32_t g_flag[NTILES];

__device__ __forceinline__ uint32_t smem_u32(const void* p) {
    uint32_t a;
    asm("{ .reg .u64 t; cvta.to.shared.u64 t, %1; cvt.u32.u64 %0, t; }" : "=r"(a) : "l"(p));
    return a;
}
__device__ __forceinline__ uint32_t ld_acq(const uint32_t* p) {
    uint32_t v;
    asm volatile("ld.global.acquire.gpu.u32 %0, [%1];" : "=r"(v) : "l"(p));
    return v;
}
__device__ __forceinline__ void st_rel(uint32_t* p, uint32_t v) {
    asm volatile("st.global.release.gpu.u32 [%0], %1;" :: "l"(p), "r"(v));
}

// ===========================================================================
// Kernel 1: FP16 MMA GEMM, CTA tile M=64 x N=256 (A read ONCE) — frozen
// (measured ~111us, realized HMMA ceiling). Clears scan flags.
// ===========================================================================
#define GBM 64
#define BKH 32

__global__ __launch_bounds__(256, 1)
void snn_gemm_f16(const float* __restrict__ A,
                  const float* __restrict__ W,
                  __half* __restrict__ H)
{
    __shared__ __align__(16) __half Asm[GBM * BKH];     // 4 KB
    __shared__ __align__(16) __half Bsm[SNN_O * BKH];   // 16 KB

    const int tid  = threadIdx.x;
    const int lane = tid & 31;
    const int wid  = tid >> 5;
    const int wm   = wid & 1;
    const int wn   = wid >> 1;
    const int g    = lane >> 2;
    const int t4   = lane & 3;

    const int bm = blockIdx.x * GBM;   // 1000 tiles

    if (tid == 0 && blockIdx.x < NTILES) g_flag[blockIdx.x] = 0;

    const uint32_t sA = smem_u32(Asm);
    const uint32_t sB = smem_u32(Bsm);

    const int arow0 = (tid >> 3);
    const int aj    = tid & 7;
    const float* Ap = A + (size_t)(bm + arow0) * SNN_I + aj * 4;
    const float* Wp = W + (size_t)arow0 * SNN_I + aj * 4;

    float4 pa[2], pb[8];
    #pragma unroll
    for (int i = 0; i < 2; i++)
        pa[i] = *(const float4*)(Ap + (size_t)(32 * i) * SNN_I);
    #pragma unroll
    for (int i = 0; i < 8; i++)
        pb[i] = *(const float4*)(Wp + (size_t)(32 * i) * SNN_I);

    float c[2][8][4];
    #pragma unroll
    for (int mt = 0; mt < 2; mt++)
        #pragma unroll
        for (int nt = 0; nt < 8; nt++)
            #pragma unroll
            for (int q = 0; q < 4; q++)
                c[mt][nt][q] = 0.0f;

    #pragma unroll 1
    for (int kt = 0; kt < SNN_I / BKH; kt++) {
        {
            const int colb = aj * 8;
            const int seg  = colb >> 4;
            const int rem  = colb & 15;
            #pragma unroll
            for (int i = 0; i < 2; i++) {
                const int row = arow0 + 32 * i;
                const uint32_t off = row * 64 + (((seg ^ ((row >> 1) & 3)) << 4) | rem);
                __half2 a0 = __floats2half2_rn(pa[i].x, pa[i].y);
                __half2 a1 = __floats2half2_rn(pa[i].z, pa[i].w);
                uint2 av = {*(uint32_t*)&a0, *(uint32_t*)&a1};
                *(uint2*)((char*)Asm + off) = av;
            }
            #pragma unroll
            for (int i = 0; i < 8; i++) {
                const int row = arow0 + 32 * i;
                const uint32_t off = row * 64 + (((seg ^ ((row >> 1) & 3)) << 4) | rem);
                __half2 b0 = __floats2half2_rn(pb[i].x, pb[i].y);
                __half2 b1 = __floats2half2_rn(pb[i].z, pb[i].w);
                uint2 bv = {*(uint32_t*)&b0, *(uint32_t*)&b1};
                *(uint2*)((char*)Bsm + off) = bv;
            }
        }
        __syncthreads();

        if (kt + 1 < SNN_I / BKH) {
            const int koff = (kt + 1) * BKH;
            #pragma unroll
            for (int i = 0; i < 2; i++)
                pa[i] = *(const float4*)(Ap + (size_t)(32 * i) * SNN_I + koff);
            #pragma unroll
            for (int i = 0; i < 8; i++)
                pb[i] = *(const float4*)(Wp + (size_t)(32 * i) * SNN_I + koff);
        }

        #pragma unroll
        for (int s = 0; s < 2; s++) {
            uint32_t af[2][4];
            #pragma unroll
            for (int mt = 0; mt < 2; mt++) {
                const int row = wm * 32 + mt * 16 + (lane & 15);
                const int seg = s * 2 + (lane >> 4);
                const uint32_t addr = sA + row * 64 + ((seg ^ ((row >> 1) & 3)) << 4);
                asm volatile(
                    "ldmatrix.sync.aligned.m8n8.x4.shared.b16 {%0,%1,%2,%3}, [%4];"
                    : "=r"(af[mt][0]), "=r"(af[mt][1]), "=r"(af[mt][2]), "=r"(af[mt][3])
                    : "r"(addr));
            }
            uint32_t bf[4][4];
            #pragma unroll
            for (int p = 0; p < 4; p++) {
                const int row = wn * 64 + p * 16 + (lane & 15);
                const int seg = s * 2 + (lane >> 4);
                const uint32_t addr = sB + row * 64 + ((seg ^ ((row >> 1) & 3)) << 4);
                asm volatile(
                    "ldmatrix.sync.aligned.m8n8.x4.shared.b16 {%0,%1,%2,%3}, [%4];"
                    : "=r"(bf[p][0]), "=r"(bf[p][1]), "=r"(bf[p][2]), "=r"(bf[p][3])
                    : "r"(addr));
            }
            #pragma unroll
            for (int mt = 0; mt < 2; mt++)
                #pragma unroll
                for (int nt = 0; nt < 8; nt++) {
                    const int p = nt >> 1, hi = nt & 1;
                    asm volatile(
                        "mma.sync.aligned.m16n8k16.row.col.f32.f16.f16.f32 "
                        "{%0,%1,%2,%3}, {%4,%5,%6,%7}, {%8,%9}, {%0,%1,%2,%3};"
                        : "+f"(c[mt][nt][0]), "+f"(c[mt][nt][1]),
                          "+f"(c[mt][nt][2]), "+f"(c[mt][nt][3])
                        : "r"(af[mt][0]), "r"(af[mt][1]), "r"(af[mt][2]), "r"(af[mt][3]),
                          "r"(bf[p][hi]), "r"(bf[p][hi + 2]));
                }
        }
        __syncthreads();
    }

    #pragma unroll
    for (int mt = 0; mt < 2; mt++) {
        #pragma unroll
        for (int nt = 0; nt < 8; nt++) {
            const int row = bm + wm * 32 + mt * 16 + g;
            const int col = wn * 64 + nt * 8 + t4 * 2;
            __half2 v0 = __floats2half2_rn(c[mt][nt][0], c[mt][nt][1]);
            __half2 v1 = __floats2half2_rn(c[mt][nt][2], c[mt][nt][3]);
            *(__half2*)(H + (size_t)row * SNN_O + col)       = v0;
            *(__half2*)(H + (size_t)(row + 8) * SNN_O + col) = v1;
        }
    }
}

// ===========================================================================
// Kernel 2: smem-staged lookback scan v2.
//   CHUNKS=10 (L=100): smem 51.2KB -> 4 CTAs/SM, 640 CTAs = 1.08 waves.
//   128 threads x 2 chains: half2 LDS (conflict-free) + STG.64 stores.
//   bid = cidx*64 + b (chunk slowest) -> lookback deadlock-free.
// ===========================================================================
#define CHUNK_BYTES (CHUNK_L * SNN_O * 2)   // 51200

__global__ __launch_bounds__(128)
void snn_scan_smem(const __half* __restrict__ H, float* __restrict__ out)
{
    extern __shared__ __align__(16) char smem[];

    const int tid  = threadIdx.x;            // chain pair: o = 2*tid, 2*tid+1
    const int cidx = blockIdx.x >> 6;        // 0..9 (slowest)
    const int b    = blockIdx.x & 63;

    const size_t gbase = ((size_t)b * SNN_T + cidx * CHUNK_L) * SNN_O;

    // bulk copy chunk into smem: 3200 uint4 / 128 thr = 25 each, coalesced
    {
        const uint4* src = (const uint4*)(H + gbase);
        uint4* dst = (uint4*)smem;
        #pragma unroll
        for (int i = 0; i < CHUNK_BYTES / 16 / 128; i++)
            dst[i * 128 + tid] = src[i * 128 + tid];
    }
    __syncthreads();

    const __half2* cp = (const __half2*)smem + tid;   // stride 128 half2 per t

    // ---- Pass A: local scan from zero (half2 smem reads) ----
    float f0 = 0.f, o0 = 0.f, f1 = 0.f, o1 = 0.f;
    #pragma unroll 1
    for (int t = 0; t < CHUNK_L; t += 5) {
        __half2 v[5];
        #pragma unroll
        for (int j = 0; j < 5; j++)
            v[j] = cp[(t + j) * (SNN_O / 2)];
        #pragma unroll
        for (int j = 0; j < 5; j++) {
            float h0 = __low2float(v[j]), h1 = __high2float(v[j]);
            float n0 = fmaf(ALPHA, f0, h0);
            float n1 = fmaf(ALPHA, f1, h1);
            o0 = fmaf(BETA, o0, f0);
            o1 = fmaf(BETA, o1, f1);
            f0 = n0; f1 = n1;
        }
    }

    // ---- Publish end states + flag ----
    g_end[((b * CHUNKS + cidx) << 7) | tid] = make_float4(f0, o0, f1, o1);
    __syncthreads();
    if (tid == 0) {
        __threadfence();
        st_rel(&g_flag[b * CHUNKS + cidx], 1u);
    }

    float* op = out + gbase + tid * 2;

    if (cidx == 0) {
        // chunk 0: local scan IS the true scan — single pass, write out now
        float ff0 = 0.f, oo0 = 0.f, ff1 = 0.f, oo1 = 0.f;
        #pragma unroll 1
        for (int t = 0; t < CHUNK_L; t += 5) {
            __half2 v[5];
            #pragma unroll
            for (int j = 0; j < 5; j++)
                v[j] = cp[(t + j) * (SNN_O / 2)];
            #pragma unroll
            for (int j = 0; j < 5; j++) {
                float h0 = __low2float(v[j]), h1 = __high2float(v[j]);
                float n0 = fmaf(ALPHA, ff0, h0);
                float n1 = fmaf(ALPHA, ff1, h1);
                oo0 = fmaf(BETA, oo0, ff0);
                oo1 = fmaf(BETA, oo1, ff1);
                ff0 = n0; ff1 = n1;
                float2 w = {oo0, oo1};
                *(float2*)(op + (t + j) * SNN_O) = w;
            }
        }
        return;
    }

    // ---- Lookback: wait for <=9 predecessors, combine via M^100 ----
    if (tid < cidx) {
        const uint32_t* fp = &g_flag[b * CHUNKS + tid];
        while (ld_acq(fp) == 0) { }
    }
    __syncthreads();

    const float aL = exp2f((float)CHUNK_L * log2f(ALPHA));
    const float bL = exp2f((float)CHUNK_L * log2f(BETA));
    const float cL = (aL - bL) / (ALPHA - BETA);

    float pf0 = 0.f, po0 = 0.f, pf1 = 0.f, po1 = 0.f;
    for (int c2 = 0; c2 < cidx; c2++) {
        const float4 e = g_end[((b * CHUNKS + c2) << 7) | tid];
        float nf0 = fmaf(aL, pf0, e.x);
        float no0 = fmaf(bL, po0, fmaf(cL, pf0, e.y));
        float nf1 = fmaf(aL, pf1, e.z);
        float no1 = fmaf(bL, po1, fmaf(cL, pf1, e.w));
        pf0 = nf0; po0 = no0; pf1 = nf1; po1 = no1;
    }

    // ---- Pass B: rescan from exact prefix, STG.64 output ----
    f0 = pf0; o0 = po0; f1 = pf1; o1 = po1;
    #pragma unroll 1
    for (int t = 0; t < CHUNK_L; t += 5) {
        __half2 v[5];
        #pragma unroll
        for (int j = 0; j < 5; j++)
            v[j] = cp[(t + j) * (SNN_O / 2)];
        #pragma unroll
        for (int j = 0; j < 5; j++) {
            float h0 = __low2float(v[j]), h1 = __high2float(v[j]);
            float n0 = fmaf(ALPHA, f0, h0);
            float n1 = fmaf(ALPHA, f1, h1);
            o0 = fmaf(BETA, o0, f0);
            o1 = fmaf(BETA, o1, f1);
            f0 = n0; f1 = n1;
            float2 w = {o0, o1};
            *(float2*)(op + (t + j) * SNN_O) = w;
        }
    }
}

// ---------------------------------------------------------------------------
extern "C" void kernel_launch(void* const* d_in, const int* in_sizes, int n_in,
                              void* d_out, int out_size)
{
    const float* inputs = (const float*)d_in[0];   // (B, T, I)
    const float* W      = (const float*)d_in[1];   // (O, I)
    float* out = (float*)d_out;                    // (B, T, O) fp32

    __half* h;
    cudaGetSymbolAddress((void**)&h, g_h);

    snn_gemm_f16<<<MROWS / GBM, 256>>>(inputs, W, h);   // 1000 CTAs

    cudaFuncSetAttribute(snn_scan_smem, cudaFuncAttributeMaxDynamicSharedMemorySize, CHUNK_BYTES);
    snn_scan_smem<<<NTILES, 128, CHUNK_BYTES>>>(h, out);
}